// round 5
// baseline (speedup 1.0000x reference)
#include <cuda_runtime.h>

#define NPATCH 196
#define NTHREADS 224

typedef unsigned long long u64;

__device__ __forceinline__ u64 mul2(u64 a, u64 b) {
    u64 d; asm("mul.rn.f32x2 %0,%1,%2;" : "=l"(d) : "l"(a), "l"(b)); return d;
}
__device__ __forceinline__ u64 add2(u64 a, u64 b) {
    u64 d; asm("add.rn.f32x2 %0,%1,%2;" : "=l"(d) : "l"(a), "l"(b)); return d;
}
__device__ __forceinline__ u64 fma2(u64 a, u64 b, u64 c) {
    u64 d; asm("fma.rn.f32x2 %0,%1,%2,%3;" : "=l"(d) : "l"(a), "l"(b), "l"(c)); return d;
}
__device__ __forceinline__ u64 pk2(float lo, float hi) {
    u64 d; asm("mov.b64 %0,{%1,%2};" : "=l"(d) : "f"(lo), "f"(hi)); return d;
}
__device__ __forceinline__ void upk(u64 v, float& lo, float& hi) {
    asm("mov.b64 {%0,%1},%2;" : "=f"(lo), "=f"(hi) : "l"(v));
}
__device__ __forceinline__ u64 neg1pk() {
    u64 d; asm("mov.b64 %0,0xBF800000BF800000;" : "=l"(d)); return d;
}

// Packed Ry on wire w (pack index bit distance kb), pack lane = q3
#define RYWP(kb, cv, sv, nsv) { \
    _Pragma("unroll") \
    for (int k = 0; k < 8; k++) { \
        if (!(k & (kb))) { \
            u64 a0 = P[k], a1 = P[k | (kb)]; \
            P[k]        = fma2((nsv), a1, mul2((cv), a0)); \
            P[k | (kb)] = fma2((cv),  a1, mul2((sv), a0)); \
        } \
    } }

__global__ __launch_bounds__(NTHREADS)
void quanv_kernel(const float* __restrict__ x,
                  const float* __restrict__ params,
                  const float* __restrict__ W,
                  const float* __restrict__ bias,
                  float* __restrict__ out)
{
    __shared__ float img[784];
    __shared__ float p0s[4];                // layer-0 params (fused into encoding angle)
    __shared__ u64  cP[3], sP[3], nsP[3];   // packed (c,c),(s,s),(-s,-s) for wires 0-2
    __shared__ float c3s, s3s;              // wire-3 layer-1 scalars
    __shared__ float wsum[7][10];
    __shared__ float slogits[10];

    const int b = blockIdx.x;
    const int t = threadIdx.x;
    const int lane = t & 31;

    // Cooperative vectorized image load: 196 x float4 = 784 floats
    if (t < NPATCH) {
        reinterpret_cast<float4*>(img)[t] =
            reinterpret_cast<const float4*>(x + b * 784)[t];
    }
    if (t < 4) {
        p0s[t] = params[t];
        float sv, cv;
        __sincosf(params[4 + t] * 0.5f, &sv, &cv);
        if (t < 3) { cP[t] = pk2(cv, cv); sP[t] = pk2(sv, sv); nsP[t] = pk2(-sv, -sv); }
        else       { c3s = cv; s3s = sv; }
    }
    __syncthreads();

    float vals[16];
    #pragma unroll
    for (int c = 0; c < 16; c++) vals[c] = 0.0f;

    if (t < NPATCH) {
        const int pr = t / 14, pc = t % 14;
        const float* base = img + (2 * pr) * 28 + 2 * pc;
        const float2 r0 = *reinterpret_cast<const float2*>(base);
        const float2 r1 = *reinterpret_cast<const float2*>(base + 28);

        float cc[4], ss[4];
        __sincosf((r0.x + p0s[0]) * 0.5f, &ss[0], &cc[0]);
        __sincosf((r0.y + p0s[1]) * 0.5f, &ss[1], &cc[1]);
        __sincosf((r1.x + p0s[2]) * 0.5f, &ss[2], &cc[2]);
        __sincosf((r1.y + p0s[3]) * 0.5f, &ss[3], &cc[3]);

        float a01[4] = { cc[0]*cc[1], cc[0]*ss[1], ss[0]*cc[1], ss[0]*ss[1] };
        float a23[4] = { cc[2]*cc[3], cc[2]*ss[3], ss[2]*cc[3], ss[2]*ss[3] };

        // Product state with ALL layer-0 CNOTs folded in as a label permutation:
        // sigma: Q0=q0^q3, Q1=q1^q0^q3, Q2=q2^q1, Q3=q3^q2
        float st[16];
        #pragma unroll
        for (int i = 0; i < 16; i++) {
            const int q0 = (i >> 3) & 1, q1 = (i >> 2) & 1, q2 = (i >> 1) & 1, q3 = i & 1;
            const int i01 = ((q0 ^ q3) << 1) | (q1 ^ q0 ^ q3);
            const int i23 = ((q2 ^ q1) << 1) | (q3 ^ q2);
            st[i] = a01[i01] * a23[i23];
        }

        // Layer-1 Ry on wire 3 applied scalar, fused into pack construction
        // (rotations on distinct wires commute, so wire-3 first is legal).
        const float cv3 = c3s, sv3 = s3s;
        u64 P[8];
        #pragma unroll
        for (int k = 0; k < 8; k++) {
            float lo = cv3 * st[2*k] - sv3 * st[2*k+1];
            float hi = sv3 * st[2*k] + cv3 * st[2*k+1];
            P[k] = pk2(lo, hi);
        }

        // Layer-1 Ry on wires 0,1,2 — packed, elementwise on q3-pairs
        {
            const u64 c0 = cP[0], s0 = sP[0], n0 = nsP[0];
            const u64 c1 = cP[1], s1 = sP[1], n1 = nsP[1];
            const u64 c2 = cP[2], s2 = sP[2], n2 = nsP[2];
            RYWP(4, c0, s0, n0);
            RYWP(2, c1, s1, n1);
            RYWP(1, c2, s2, n2);
        }

        // Measurement with the 4 final CNOTs folded into sign masks:
        // z0: q1^q2^q3   z1: q0^q1   z2: q0^q1^q2   z3: q0^q1^q2^q3
        const u64 NEG1 = neg1pk();
        #define SUB2(a, bb) fma2((bb), NEG1, (a))

        u64 Q[8];
        #pragma unroll
        for (int k = 0; k < 8; k++) Q[k] = mul2(P[k], P[k]);   // probabilities, packed

        // q0 stage (k ^ 4); k = q1*2 + q2 afterwards
        u64 Sp[4], Sm[4];
        #pragma unroll
        for (int k = 0; k < 4; k++) { Sp[k] = add2(Q[k], Q[k+4]); Sm[k] = SUB2(Q[k], Q[k+4]); }

        // z0 (q0:+, q1:-, q2:-, q3:-): from Sp
        u64 T0 = SUB2(Sp[0], Sp[2]);      // q1 minus
        u64 T1 = SUB2(Sp[1], Sp[3]);
        u64 H0 = SUB2(T0, T1);            // q2 minus
        // z1 (q0:-, q1:-, q2:+, q3:+): from Sm
        u64 F0 = add2(Sm[0], Sm[1]);      // q2 plus
        u64 F1 = add2(Sm[2], Sm[3]);
        u64 H1 = SUB2(F0, F1);            // q1 minus
        // z2 (q0:-, q1:-, q2:-, q3:+) and z3 (same, q3:-): from Sm
        u64 G0 = SUB2(Sm[0], Sm[1]);      // q2 minus
        u64 G1 = SUB2(Sm[2], Sm[3]);
        u64 H2 = SUB2(G0, G1);            // q1 minus

        float h0l, h0h, h1l, h1h, h2l, h2h;
        upk(H0, h0l, h0h); upk(H1, h1l, h1h); upk(H2, h2l, h2h);
        float z0 = h0l - h0h;
        float z1 = h1l + h1h;
        float z2 = h2l + h2h;
        float z3 = h2l - h2h;

        // Per-patch linear partials, packed: feat f = 4*t + wire; W row-major [10,784]
        const u64 z01 = pk2(z0, z1), z23 = pk2(z2, z3);
        #pragma unroll
        for (int c = 0; c < 10; c++) {
            u64 w01, w23;
            asm("ld.global.nc.v2.b64 {%0,%1},[%2];"
                : "=l"(w01), "=l"(w23)
                : "l"(W + c * 784 + 4 * t));
            u64 acc = fma2(z23, w23, mul2(z01, w01));
            float alo, ahi; upk(acc, alo, ahi);
            vals[c] = alo + ahi;
        }
        #undef SUB2
    }

    // Multi-value butterfly: split the class set each stage.
    #pragma unroll
    for (int stage = 0; stage < 4; stage++) {
        const int m = 1 << stage;
        const int h = 8 >> stage;
        const bool hi = (lane & m) != 0;
        #pragma unroll
        for (int c = 0; c < h; c++) {
            float send = hi ? vals[c]     : vals[c + h];
            float keep = hi ? vals[c + h] : vals[c];
            vals[c] = keep + __shfl_xor_sync(0xffffffffu, send, m);
        }
    }
    vals[0] += __shfl_xor_sync(0xffffffffu, vals[0], 16);

    const int cls = __brev(lane) >> 28;   // bitrev4 of lane&15
    if (lane < 16 && cls < 10) wsum[t >> 5][cls] = vals[0];
    __syncthreads();

    if (t < 10) {
        float v = bias[t];
        #pragma unroll
        for (int w = 0; w < 7; w++) v += wsum[w][t];
        slogits[t] = v;
    }
    __syncthreads();

    if (t < 10) {
        float m = slogits[0];
        #pragma unroll
        for (int c = 1; c < 10; c++) m = fmaxf(m, slogits[c]);
        float se = 0.0f;
        #pragma unroll
        for (int c = 0; c < 10; c++) se += __expf(slogits[c] - m);
        out[b * 10 + t] = slogits[t] - m - __logf(se);
    }
}

extern "C" void kernel_launch(void* const* d_in, const int* in_sizes, int n_in,
                              void* d_out, int out_size) {
    const float* x      = (const float*)d_in[0];   // [8192, 28, 28]
    const float* params = (const float*)d_in[1];   // [2, 4]
    const float* W      = (const float*)d_in[2];   // [10, 784]
    const float* bias   = (const float*)d_in[3];   // [10]
    float* out          = (float*)d_out;           // [8192, 10]

    const int B = in_sizes[0] / 784;
    quanv_kernel<<<B, NTHREADS>>>(x, params, W, bias, out);
}

// round 6
// speedup vs baseline: 1.0011x; 1.0011x over previous
#include <cuda_runtime.h>

#define NPATCH 196
#define NTHREADS 224

typedef unsigned long long u64;

__device__ __forceinline__ u64 mul2(u64 a, u64 b) {
    u64 d; asm("mul.rn.f32x2 %0,%1,%2;" : "=l"(d) : "l"(a), "l"(b)); return d;
}
__device__ __forceinline__ u64 add2(u64 a, u64 b) {
    u64 d; asm("add.rn.f32x2 %0,%1,%2;" : "=l"(d) : "l"(a), "l"(b)); return d;
}
__device__ __forceinline__ u64 fma2(u64 a, u64 b, u64 c) {
    u64 d; asm("fma.rn.f32x2 %0,%1,%2,%3;" : "=l"(d) : "l"(a), "l"(b), "l"(c)); return d;
}
__device__ __forceinline__ u64 pk2(float lo, float hi) {
    u64 d; asm("mov.b64 %0,{%1,%2};" : "=l"(d) : "f"(lo), "f"(hi)); return d;
}
__device__ __forceinline__ void upk(u64 v, float& lo, float& hi) {
    asm("mov.b64 {%0,%1},%2;" : "=f"(lo), "=f"(hi) : "l"(v));
}
__device__ __forceinline__ u64 neg1pk() {
    u64 d; asm("mov.b64 %0,0xBF800000BF800000;" : "=l"(d)); return d;
}

// Packed Ry stage on pack-index bit kb; constants read from smem per-stage
// (keeps only 3 u64 constants live at a time).
#define RYWP(kb, w) { \
    const u64 cv = cP[w], sv = sP[w], nsv = nsP[w]; \
    _Pragma("unroll") \
    for (int k = 0; k < 8; k++) { \
        if (!(k & (kb))) { \
            u64 a0 = P[k], a1 = P[k | (kb)]; \
            P[k]        = fma2(nsv, a1, mul2(cv, a0)); \
            P[k | (kb)] = fma2(cv,  a1, mul2(sv, a0)); \
        } \
    } }

__global__ __launch_bounds__(NTHREADS, 8)
void quanv_kernel(const float* __restrict__ x,
                  const float* __restrict__ params,
                  const float* __restrict__ W,
                  const float* __restrict__ bias,
                  float* __restrict__ out)
{
    __shared__ float img[784];
    __shared__ float p0s[4];                // layer-0 params (fused into encoding angle)
    __shared__ u64  cP[3], sP[3], nsP[3];   // packed (c,c),(s,s),(-s,-s) for wires 0-2
    __shared__ float c3s, s3s;              // wire-3 layer-1 scalars
    __shared__ float wsum[7][10];

    const int b = blockIdx.x;
    const int t = threadIdx.x;
    const int lane = t & 31;

    // Cooperative vectorized image load: 196 x float4 = 784 floats
    if (t < NPATCH) {
        reinterpret_cast<float4*>(img)[t] =
            reinterpret_cast<const float4*>(x + b * 784)[t];
    }
    if (t < 4) {
        p0s[t] = params[t];
        float sv, cv;
        __sincosf(params[4 + t] * 0.5f, &sv, &cv);
        if (t < 3) { cP[t] = pk2(cv, cv); sP[t] = pk2(sv, sv); nsP[t] = pk2(-sv, -sv); }
        else       { c3s = cv; s3s = sv; }
    }
    __syncthreads();

    float vals[16];
    #pragma unroll
    for (int c = 0; c < 16; c++) vals[c] = 0.0f;

    if (t < NPATCH) {
        const int pr = t / 14, pc = t % 14;
        const float* base = img + (2 * pr) * 28 + 2 * pc;
        const float2 r0 = *reinterpret_cast<const float2*>(base);
        const float2 r1 = *reinterpret_cast<const float2*>(base + 28);

        float cc[4], ss[4];
        __sincosf((r0.x + p0s[0]) * 0.5f, &ss[0], &cc[0]);
        __sincosf((r0.y + p0s[1]) * 0.5f, &ss[1], &cc[1]);
        __sincosf((r1.x + p0s[2]) * 0.5f, &ss[2], &cc[2]);
        __sincosf((r1.y + p0s[3]) * 0.5f, &ss[3], &cc[3]);

        float a01[4] = { cc[0]*cc[1], cc[0]*ss[1], ss[0]*cc[1], ss[0]*ss[1] };
        float a23[4] = { cc[2]*cc[3], cc[2]*ss[3], ss[2]*cc[3], ss[2]*ss[3] };

        // Product state with ALL layer-0 CNOTs folded in as a label permutation:
        // sigma: Q0=q0^q3, Q1=q1^q0^q3, Q2=q2^q1, Q3=q3^q2
        float st[16];
        #pragma unroll
        for (int i = 0; i < 16; i++) {
            const int q0 = (i >> 3) & 1, q1 = (i >> 2) & 1, q2 = (i >> 1) & 1, q3 = i & 1;
            const int i01 = ((q0 ^ q3) << 1) | (q1 ^ q0 ^ q3);
            const int i23 = ((q2 ^ q1) << 1) | (q3 ^ q2);
            st[i] = a01[i01] * a23[i23];
        }

        // Layer-1 Ry on wire 3 applied scalar, fused into pack construction
        // (rotations on distinct wires commute, so wire-3 first is legal).
        const float cv3 = c3s, sv3 = s3s;
        u64 P[8];
        #pragma unroll
        for (int k = 0; k < 8; k++) {
            float lo = cv3 * st[2*k] - sv3 * st[2*k+1];
            float hi = sv3 * st[2*k] + cv3 * st[2*k+1];
            P[k] = pk2(lo, hi);
        }

        // Layer-1 Ry on wires 0,1,2 — packed, elementwise on q3-pairs
        RYWP(4, 0);
        RYWP(2, 1);
        RYWP(1, 2);

        // Measurement with the 4 final CNOTs folded into sign masks:
        // z0: q1^q2^q3   z1: q0^q1   z2: q0^q1^q2   z3: q0^q1^q2^q3
        const u64 NEG1 = neg1pk();
        #define SUB2(a, bb) fma2((bb), NEG1, (a))

        u64 Q[8];
        #pragma unroll
        for (int k = 0; k < 8; k++) Q[k] = mul2(P[k], P[k]);   // probabilities, packed

        u64 Sp[4], Sm[4];
        #pragma unroll
        for (int k = 0; k < 4; k++) { Sp[k] = add2(Q[k], Q[k+4]); Sm[k] = SUB2(Q[k], Q[k+4]); }

        u64 T0 = SUB2(Sp[0], Sp[2]);
        u64 T1 = SUB2(Sp[1], Sp[3]);
        u64 H0 = SUB2(T0, T1);
        u64 F0 = add2(Sm[0], Sm[1]);
        u64 F1 = add2(Sm[2], Sm[3]);
        u64 H1 = SUB2(F0, F1);
        u64 G0 = SUB2(Sm[0], Sm[1]);
        u64 G1 = SUB2(Sm[2], Sm[3]);
        u64 H2 = SUB2(G0, G1);

        float h0l, h0h, h1l, h1h, h2l, h2h;
        upk(H0, h0l, h0h); upk(H1, h1l, h1h); upk(H2, h2l, h2h);
        float z0 = h0l - h0h;
        float z1 = h1l + h1h;
        float z2 = h2l + h2h;
        float z3 = h2l - h2h;

        // Per-patch linear partials, packed: feat f = 4*t + wire; W row-major [10,784]
        const u64 z01 = pk2(z0, z1), z23 = pk2(z2, z3);
        #pragma unroll
        for (int c = 0; c < 10; c++) {
            u64 w01, w23;
            asm("ld.global.nc.v2.b64 {%0,%1},[%2];"
                : "=l"(w01), "=l"(w23)
                : "l"(W + c * 784 + 4 * t));
            u64 acc = fma2(z23, w23, mul2(z01, w01));
            float alo, ahi; upk(acc, alo, ahi);
            vals[c] = alo + ahi;
        }
        #undef SUB2
    }

    // Multi-value butterfly: split the class set each stage.
    #pragma unroll
    for (int stage = 0; stage < 4; stage++) {
        const int m = 1 << stage;
        const int h = 8 >> stage;
        const bool hi = (lane & m) != 0;
        #pragma unroll
        for (int c = 0; c < h; c++) {
            float send = hi ? vals[c]     : vals[c + h];
            float keep = hi ? vals[c + h] : vals[c];
            vals[c] = keep + __shfl_xor_sync(0xffffffffu, send, m);
        }
    }
    vals[0] += __shfl_xor_sync(0xffffffffu, vals[0], 16);

    const int cls = __brev(lane) >> 28;   // bitrev4 of lane&15
    if (lane < 16 && cls < 10) wsum[t >> 5][cls] = vals[0];
    __syncthreads();

    // Warp 0 finishes: cross-warp combine + log_softmax entirely in shuffles.
    if (t < 32) {
        float logit = -__int_as_float(0x7f800000);  // -inf for lanes >= 10
        if (t < 10) {
            float v = bias[t];
            #pragma unroll
            for (int w = 0; w < 7; w++) v += wsum[w][t];
            logit = v;
        }
        float m = logit;
        #pragma unroll
        for (int off = 8; off > 0; off >>= 1)
            m = fmaxf(m, __shfl_xor_sync(0xffffffffu, m, off));
        float e = (t < 10) ? __expf(logit - m) : 0.0f;
        #pragma unroll
        for (int off = 8; off > 0; off >>= 1)
            e += __shfl_xor_sync(0xffffffffu, e, off);
        if (t < 10) out[b * 10 + t] = logit - m - __logf(e);
    }
}

extern "C" void kernel_launch(void* const* d_in, const int* in_sizes, int n_in,
                              void* d_out, int out_size) {
    const float* x      = (const float*)d_in[0];   // [8192, 28, 28]
    const float* params = (const float*)d_in[1];   // [2, 4]
    const float* W      = (const float*)d_in[2];   // [10, 784]
    const float* bias   = (const float*)d_in[3];   // [10]
    float* out          = (float*)d_out;           // [8192, 10]

    const int B = in_sizes[0] / 784;
    quanv_kernel<<<B, NTHREADS>>>(x, params, W, bias, out);
}